// round 14
// baseline (speedup 1.0000x reference)
#include <cuda_runtime.h>
#include <cuda_fp16.h>
#include <math.h>
#include <stdint.h>

#define T_TOK 2048
#define HDIM  1024
#define FFND  4096
#define NE    8
#define NF2   8192   // 2*FFND
#define NPAIR (2*T_TOK)

// ---------------- scratch (static device globals; no allocation) ------------
// NOTE: never pass these as kernel args from host (host shadow != device ptr).
__device__ int    d_count[NE];
__device__ int    d_list[NE * T_TOK];
__device__ float  d_wgt[NPAIR];
__device__ __half d_xh[(size_t)T_TOK * HDIM];         // x fp16
__device__ __half d_w13h[(size_t)NE * NF2 * HDIM];    // w13 fp16 (128 MB)
__device__ __half d_w2h[(size_t)NE * HDIM * FFND];    // w2 fp16 (64 MB)
__device__ __half d_zh[(size_t)NPAIR * NF2];          // g|u fp16
__device__ __half d_acth[(size_t)NPAIR * FFND];       // silu(g)*u fp16
__device__ float  d_y[(size_t)NPAIR * HDIM];

// ---------------------------------------------------------------------------
__global__ void zero_counts_kernel() {
    if (threadIdx.x < NE) d_count[threadIdx.x] = 0;
}

__device__ __forceinline__ uint32_t pack2h(float lo, float hi) {
    uint32_t r;
    asm("cvt.rn.f16x2.f32 %0, %1, %2;" : "=r"(r) : "f"(hi), "f"(lo));
    return r;
}

// One warp per token: router logits, top-2 softmax weights, expert compaction.
__global__ void router_kernel(const float* __restrict__ x,
                              const float* __restrict__ gw,
                              float* __restrict__ rlogits) {
    int gwarp = (blockIdx.x * blockDim.x + threadIdx.x) >> 5;
    int lane  = threadIdx.x & 31;
    if (gwarp >= T_TOK) return;
    const float* xr = x + (size_t)gwarp * HDIM;

    float acc[NE];
#pragma unroll
    for (int e = 0; e < NE; e++) acc[e] = 0.f;
    for (int h = lane; h < HDIM; h += 32) {
        float xv = xr[h];
#pragma unroll
        for (int e = 0; e < NE; e++) acc[e] += xv * gw[e * HDIM + h];
    }
#pragma unroll
    for (int e = 0; e < NE; e++)
#pragma unroll
        for (int off = 16; off; off >>= 1)
            acc[e] += __shfl_xor_sync(0xffffffffu, acc[e], off);

    if (lane == 0) {
#pragma unroll
        for (int e = 0; e < NE; e++) rlogits[gwarp * NE + e] = acc[e];
        int e0 = 0;
#pragma unroll
        for (int e = 1; e < NE; e++) if (acc[e] > acc[e0]) e0 = e;
        int e1 = (e0 == 0) ? 1 : 0;
#pragma unroll
        for (int e = 0; e < NE; e++)
            if (e != e0 && acc[e] > acc[e1]) e1 = e;
        float p1 = __expf(acc[e1] - acc[e0]);
        float inv = 1.0f / (1.0f + p1);
        d_wgt[gwarp * 2 + 0] = inv;
        d_wgt[gwarp * 2 + 1] = p1 * inv;

        int pos0 = atomicAdd(&d_count[e0], 1);
        d_list[e0 * T_TOK + pos0] = gwarp * 2 + 0;
        int pos1 = atomicAdd(&d_count[e1], 1);
        d_list[e1 * T_TOK + pos1] = gwarp * 2 + 1;
    }
}

// Convert x to fp16.
__global__ void convert_x_kernel(const float* __restrict__ x) {
    int i8 = blockIdx.x * blockDim.x + threadIdx.x;   // over T*H/8
    if (i8 >= T_TOK * HDIM / 8) return;
    float4 v0 = ((const float4*)x)[i8 * 2 + 0];
    float4 v1 = ((const float4*)x)[i8 * 2 + 1];
    uint4 u;
    u.x = pack2h(v0.x, v0.y);
    u.y = pack2h(v0.z, v0.w);
    u.z = pack2h(v1.x, v1.y);
    u.w = pack2h(v1.z, v1.w);
    ((uint4*)d_xh)[i8] = u;
}

// Convert w13 + w2 to fp16 (8 floats / thread, single grid).
__global__ void convert_w_kernel(const float* __restrict__ w13,
                                 const float* __restrict__ w2) {
    size_t i8 = (size_t)blockIdx.x * blockDim.x + threadIdx.x;
    const size_t n13 = (size_t)NE * NF2 * HDIM / 8;   // 8388608
    const size_t n2  = (size_t)NE * HDIM * FFND / 8;  // 4194304
    if (i8 < n13) {
        float4 v0 = ((const float4*)w13)[i8 * 2 + 0];
        float4 v1 = ((const float4*)w13)[i8 * 2 + 1];
        uint4 u;
        u.x = pack2h(v0.x, v0.y); u.y = pack2h(v0.z, v0.w);
        u.z = pack2h(v1.x, v1.y); u.w = pack2h(v1.z, v1.w);
        ((uint4*)d_w13h)[i8] = u;
    } else if (i8 < n13 + n2) {
        size_t j = i8 - n13;
        float4 v0 = ((const float4*)w2)[j * 2 + 0];
        float4 v1 = ((const float4*)w2)[j * 2 + 1];
        uint4 u;
        u.x = pack2h(v0.x, v0.y); u.y = pack2h(v0.z, v0.w);
        u.z = pack2h(v1.x, v1.y); u.w = pack2h(v1.z, v1.w);
        ((uint4*)d_w2h)[j] = u;
    }
}

// ---------------- mma helper -------------------------------------------------
__device__ __forceinline__ void mma_f16(float* d, const uint32_t* a, const uint32_t* b) {
    asm volatile(
        "mma.sync.aligned.m16n8k16.row.col.f32.f16.f16.f32 "
        "{%0,%1,%2,%3}, {%4,%5,%6,%7}, {%8,%9}, {%0,%1,%2,%3};\n"
        : "+f"(d[0]), "+f"(d[1]), "+f"(d[2]), "+f"(d[3])
        : "r"(a[0]), "r"(a[1]), "r"(a[2]), "r"(a[3]), "r"(b[0]), "r"(b[1]));
}

// ---------------- fp16 GEMM, 256x128 tile, 512 threads, double-buffered -----
// C[pair, n0..] = A_row(pair) . B[e][n]^T ; 256x128 block tile, BK=32,
// 16 warps (4m x 4n), warp tile 64x32 (identical inner code to verified R13).
// MODE 0: A = d_xh (row = pair>>1), B = d_w13h, C = d_zh fp16 (stride NF2)
// MODE 1: A = d_acth (row = pair),  B = d_w2h,  C = d_y fp32 (stride HDIM)
#define ROWH 40   // SMEM row stride in halves (80 B); conflict-free
// dynamic SMEM layout (halves): As stage s at s*10240; Bs stage s at 20480+s*5120
#define AS_OFF(s) ((s) * 10240)
#define BS_OFF(s) (20480 + (s) * 5120)
#define SMEM_HALVES 30720   // 61440 bytes

template<int KDIM, int BROWS, int MODE>
__global__ __launch_bounds__(512)
void gemm_f16_kernel() {
    extern __shared__ __half dynsm[];
    __shared__ int sPair[256];

    const __half* A  = (MODE == 0) ? d_xh   : d_acth;
    const __half* Bw = (MODE == 0) ? d_w13h : d_w2h;
    const int ASHIFT = (MODE == 0) ? 1 : 0;

    int e   = blockIdx.z;
    int cnt = d_count[e];
    int m0  = blockIdx.x * 256;
    if (m0 >= cnt) return;
    int n0  = blockIdx.y * 128;

    int tid = threadIdx.x;
    if (tid < 256) {
        int m = m0 + tid;
        sPair[tid] = d_list[e * T_TOK + (m < cnt ? m : cnt - 1)];
    }
    __syncthreads();

    // A load geometry: 256 rows, 16 halves/thread (2 uint4)
    int aRow = tid >> 1;            // 0..255
    int aHc  = (tid & 1) * 16;      // 0/16
    // B load geometry: 128 rows, 8 halves/thread (1 uint4)
    int bRow = tid >> 2;            // 0..127
    int bHc  = (tid & 3) * 8;       // 0,8,16,24

    const __half* aPtr = A  + (size_t)(sPair[aRow] >> ASHIFT) * KDIM + aHc;
    const __half* bPtr = Bw + ((size_t)e * BROWS + n0 + bRow) * KDIM + bHc;

    int warp = tid >> 5;            // 0..15
    int lane = tid & 31;
    int wm = warp & 3;              // 4 x 64-row slabs
    int wn = warp >> 2;             // 4 x 32-col slabs
    int g  = lane >> 2;
    int tg = lane & 3;

    float acc[4][4][4];
#pragma unroll
    for (int i = 0; i < 4; i++)
#pragma unroll
        for (int j = 0; j < 4; j++)
#pragma unroll
            for (int r = 0; r < 4; r++) acc[i][j][r] = 0.f;

    // prologue: chunk 0 -> regs -> stage 0
    uint4 fa0 = *(const uint4*)(aPtr);
    uint4 fa1 = *(const uint4*)(aPtr + 8);
    uint4 fb0 = *(const uint4*)(bPtr);
    *(uint4*)&dynsm[AS_OFF(0) + aRow * ROWH + aHc + 0] = fa0;
    *(uint4*)&dynsm[AS_OFF(0) + aRow * ROWH + aHc + 8] = fa1;
    *(uint4*)&dynsm[BS_OFF(0) + bRow * ROWH + bHc] = fb0;
    __syncthreads();

    const int NCHUNK = KDIM / 32;
    for (int kc = 0; kc < NCHUNK; kc++) {
        int cur = kc & 1;
        int nxt = cur ^ 1;
        bool more = (kc + 1 < NCHUNK);

        if (more) {
            const __half* ap = aPtr + (kc + 1) * 32;
            const __half* bp = bPtr + (kc + 1) * 32;
            fa0 = *(const uint4*)(ap);
            fa1 = *(const uint4*)(ap + 8);
            fb0 = *(const uint4*)(bp);
        }

        const __half* Acur = &dynsm[AS_OFF(cur)];
        const __half* Bcur = &dynsm[BS_OFF(cur)];
#pragma unroll
        for (int s = 0; s < 2; s++) {
            int k0 = s * 16;
            uint32_t afr[4][4], bfr[4][2];
#pragma unroll
            for (int i = 0; i < 4; i++) {
                int R = wm * 64 + i * 16;
                afr[i][0] = *(const uint32_t*)&Acur[(R + g    ) * ROWH + k0 + 2 * tg    ];
                afr[i][1] = *(const uint32_t*)&Acur[(R + g + 8) * ROWH + k0 + 2 * tg    ];
                afr[i][2] = *(const uint32_t*)&Acur[(R + g    ) * ROWH + k0 + 2 * tg + 8];
                afr[i][3] = *(const uint32_t*)&Acur[(R + g + 8) * ROWH + k0 + 2 * tg + 8];
            }
#pragma unroll
            for (int j = 0; j < 4; j++) {
                int N = wn * 32 + j * 8;
                bfr[j][0] = *(const uint32_t*)&Bcur[(N + g) * ROWH + k0 + 2 * tg    ];
                bfr[j][1] = *(const uint32_t*)&Bcur[(N + g) * ROWH + k0 + 2 * tg + 8];
            }
#pragma unroll
            for (int i = 0; i < 4; i++)
#pragma unroll
                for (int j = 0; j < 4; j++)
                    mma_f16(acc[i][j], afr[i], bfr[j]);
        }

        if (more) {
            *(uint4*)&dynsm[AS_OFF(nxt) + aRow * ROWH + aHc + 0] = fa0;
            *(uint4*)&dynsm[AS_OFF(nxt) + aRow * ROWH + aHc + 8] = fa1;
            *(uint4*)&dynsm[BS_OFF(nxt) + bRow * ROWH + bHc] = fb0;
        }
        __syncthreads();
    }

    // epilogue (identical structure to verified R13)
#pragma unroll
    for (int i = 0; i < 4; i++) {
#pragma unroll
        for (int rr = 0; rr < 2; rr++) {
            int mloc = wm * 64 + i * 16 + rr * 8 + g;
            if (m0 + mloc < cnt) {
                int p = sPair[mloc];
                if (MODE == 0) {
                    __half* dst = d_zh + (size_t)p * NF2 + n0 + wn * 32 + tg * 2;
#pragma unroll
                    for (int j = 0; j < 4; j++)
                        *(uint32_t*)(dst + j * 8) =
                            pack2h(acc[i][j][rr * 2 + 0], acc[i][j][rr * 2 + 1]);
                } else {
                    float* dst = d_y + (size_t)p * HDIM + n0 + wn * 32 + tg * 2;
#pragma unroll
                    for (int j = 0; j < 4; j++) {
                        float2 v;
                        v.x = acc[i][j][rr * 2 + 0];
                        v.y = acc[i][j][rr * 2 + 1];
                        *(float2*)(dst + j * 8) = v;
                    }
                }
            }
        }
    }
}

// ---------------- act: silu(g)*u, half in / half out -------------------------
__global__ void act_kernel() {
    int i8 = blockIdx.x * blockDim.x + threadIdx.x;   // over NPAIR*FFND/8
    int p  = i8 >> 9;                                 // / (FFND/8)
    int f8 = i8 & 511;
    if (p >= NPAIR) return;
    const uint4* gp = (const uint4*)(d_zh + (size_t)p * NF2) + f8;
    const uint4* up = (const uint4*)(d_zh + (size_t)p * NF2 + FFND) + f8;
    uint4 gu = *gp, uu = *up, o;
    const __half2* gh = (const __half2*)&gu;
    const __half2* uh = (const __half2*)&uu;
    uint32_t* oh = (uint32_t*)&o;
#pragma unroll
    for (int q = 0; q < 4; q++) {
        float2 gf = __half22float2(gh[q]);
        float2 uf = __half22float2(uh[q]);
        float r0 = gf.x / (1.0f + __expf(-gf.x)) * uf.x;
        float r1 = gf.y / (1.0f + __expf(-gf.y)) * uf.y;
        oh[q] = pack2h(r0, r1);
    }
    ((uint4*)(d_acth + (size_t)p * FFND))[f8] = o;
}

// ---------------- combine: out[t] = w0*y[2t] + w1*y[2t+1] -------------------
__global__ void combine_kernel(float* __restrict__ out) {
    int i4 = blockIdx.x * blockDim.x + threadIdx.x;
    int t  = i4 >> 8;
    int h4 = i4 & 255;
    if (t >= T_TOK) return;
    float w0 = d_wgt[2 * t], w1 = d_wgt[2 * t + 1];
    const float4* y0 = (const float4*)(d_y + (size_t)(2 * t) * HDIM) + h4;
    const float4* y1 = (const float4*)(d_y + (size_t)(2 * t + 1) * HDIM) + h4;
    float4 a = *y0, b = *y1, r;
    r.x = w0 * a.x + w1 * b.x;
    r.y = w0 * a.y + w1 * b.y;
    r.z = w0 * a.z + w1 * b.z;
    r.w = w0 * a.w + w1 * b.w;
    ((float4*)(out + (size_t)t * HDIM))[h4] = r;
}

// ---------------------------------------------------------------------------
extern "C" void kernel_launch(void* const* d_in, const int* in_sizes, int n_in,
                              void* d_out, int out_size) {
    const float* x   = (const float*)d_in[0];
    const float* gw  = (const float*)d_in[1];
    const float* w13 = (const float*)d_in[2];
    const float* w2  = (const float*)d_in[3];
    float* out = (float*)d_out;
    float* rlogits = out + (size_t)T_TOK * HDIM;

    const int smemBytes = SMEM_HALVES * 2;   // 61440
    static int attrDone = 0;
    if (!attrDone) {
        cudaFuncSetAttribute(gemm_f16_kernel<HDIM, NF2, 0>,
                             cudaFuncAttributeMaxDynamicSharedMemorySize, smemBytes);
        cudaFuncSetAttribute(gemm_f16_kernel<FFND, HDIM, 1>,
                             cudaFuncAttributeMaxDynamicSharedMemorySize, smemBytes);
        attrDone = 1;
    }

    zero_counts_kernel<<<1, 32>>>();
    router_kernel<<<T_TOK / 8, 256>>>(x, gw, rlogits);
    convert_x_kernel<<<(T_TOK * HDIM / 8 + 255) / 256, 256>>>(x);
    convert_w_kernel<<<49152, 256>>>(w13, w2);

    // GEMM1 (fp16): z_h = x_h . w13_h[e]^T, K=1024
    dim3 g1(T_TOK / 256, NF2 / 128, NE);      // (8, 64, 8)
    gemm_f16_kernel<HDIM, NF2, 0><<<g1, 512, smemBytes>>>();

    act_kernel<<<(NPAIR * FFND / 8) / 256, 256>>>();

    // GEMM2 (fp16): y = act_h . w2_h[e]^T, K=4096
    dim3 g2(T_TOK / 256, HDIM / 128, NE);     // (8, 8, 8)
    gemm_f16_kernel<FFND, HDIM, 1><<<g2, 512, smemBytes>>>();

    combine_kernel<<<(T_TOK * HDIM / 4) / 256, 256>>>(out);
}

// round 16
// speedup vs baseline: 1.5910x; 1.5910x over previous
#include <cuda_runtime.h>
#include <cuda_fp16.h>
#include <math.h>
#include <stdint.h>

#define T_TOK 2048
#define HDIM  1024
#define FFND  4096
#define NE    8
#define NF2   8192   // 2*FFND
#define NPAIR (2*T_TOK)

// ---------------- scratch (static device globals; no allocation) ------------
// NOTE: never pass these as kernel args from host (host shadow != device ptr).
__device__ int    d_count[NE];
__device__ int    d_list[NE * T_TOK];
__device__ float  d_wgt[NPAIR];
__device__ __half d_xh[(size_t)T_TOK * HDIM];         // x fp16
__device__ __half d_w13h[(size_t)NE * NF2 * HDIM];    // w13 fp16 (128 MB)
__device__ __half d_w2h[(size_t)NE * HDIM * FFND];    // w2 fp16 (64 MB)
__device__ __half d_zh[(size_t)NPAIR * NF2];          // g|u fp16
__device__ __half d_acth[(size_t)NPAIR * FFND];       // silu(g)*u fp16
__device__ float  d_y[(size_t)NPAIR * HDIM];

// ---------------------------------------------------------------------------
__global__ void zero_counts_kernel() {
    if (threadIdx.x < NE) d_count[threadIdx.x] = 0;
}

__device__ __forceinline__ uint32_t pack2h(float lo, float hi) {
    uint32_t r;
    asm("cvt.rn.f16x2.f32 %0, %1, %2;" : "=r"(r) : "f"(hi), "f"(lo));
    return r;
}

__device__ __forceinline__ void cp16(uint32_t smem_dst, const void* gsrc) {
    asm volatile("cp.async.ca.shared.global [%0], [%1], 16;" :: "r"(smem_dst), "l"(gsrc));
}

// One warp per token: router logits, top-2 softmax weights, expert compaction.
__global__ void router_kernel(const float* __restrict__ x,
                              const float* __restrict__ gw,
                              float* __restrict__ rlogits) {
    int gwarp = (blockIdx.x * blockDim.x + threadIdx.x) >> 5;
    int lane  = threadIdx.x & 31;
    if (gwarp >= T_TOK) return;
    const float* xr = x + (size_t)gwarp * HDIM;

    float acc[NE];
#pragma unroll
    for (int e = 0; e < NE; e++) acc[e] = 0.f;
    for (int h = lane; h < HDIM; h += 32) {
        float xv = xr[h];
#pragma unroll
        for (int e = 0; e < NE; e++) acc[e] += xv * gw[e * HDIM + h];
    }
#pragma unroll
    for (int e = 0; e < NE; e++)
#pragma unroll
        for (int off = 16; off; off >>= 1)
            acc[e] += __shfl_xor_sync(0xffffffffu, acc[e], off);

    if (lane == 0) {
#pragma unroll
        for (int e = 0; e < NE; e++) rlogits[gwarp * NE + e] = acc[e];
        int e0 = 0;
#pragma unroll
        for (int e = 1; e < NE; e++) if (acc[e] > acc[e0]) e0 = e;
        int e1 = (e0 == 0) ? 1 : 0;
#pragma unroll
        for (int e = 0; e < NE; e++)
            if (e != e0 && acc[e] > acc[e1]) e1 = e;
        float p1 = __expf(acc[e1] - acc[e0]);
        float inv = 1.0f / (1.0f + p1);
        d_wgt[gwarp * 2 + 0] = inv;
        d_wgt[gwarp * 2 + 1] = p1 * inv;

        int pos0 = atomicAdd(&d_count[e0], 1);
        d_list[e0 * T_TOK + pos0] = gwarp * 2 + 0;
        int pos1 = atomicAdd(&d_count[e1], 1);
        d_list[e1 * T_TOK + pos1] = gwarp * 2 + 1;
    }
}

// Convert x to fp16.
__global__ void convert_x_kernel(const float* __restrict__ x) {
    int i8 = blockIdx.x * blockDim.x + threadIdx.x;   // over T*H/8
    if (i8 >= T_TOK * HDIM / 8) return;
    float4 v0 = ((const float4*)x)[i8 * 2 + 0];
    float4 v1 = ((const float4*)x)[i8 * 2 + 1];
    uint4 u;
    u.x = pack2h(v0.x, v0.y);
    u.y = pack2h(v0.z, v0.w);
    u.z = pack2h(v1.x, v1.y);
    u.w = pack2h(v1.z, v1.w);
    ((uint4*)d_xh)[i8] = u;
}

// Convert w13 + w2 to fp16 (8 floats / thread, single grid).
__global__ void convert_w_kernel(const float* __restrict__ w13,
                                 const float* __restrict__ w2) {
    size_t i8 = (size_t)blockIdx.x * blockDim.x + threadIdx.x;
    const size_t n13 = (size_t)NE * NF2 * HDIM / 8;   // 8388608
    const size_t n2  = (size_t)NE * HDIM * FFND / 8;  // 4194304
    if (i8 < n13) {
        float4 v0 = ((const float4*)w13)[i8 * 2 + 0];
        float4 v1 = ((const float4*)w13)[i8 * 2 + 1];
        uint4 u;
        u.x = pack2h(v0.x, v0.y); u.y = pack2h(v0.z, v0.w);
        u.z = pack2h(v1.x, v1.y); u.w = pack2h(v1.z, v1.w);
        ((uint4*)d_w13h)[i8] = u;
    } else if (i8 < n13 + n2) {
        size_t j = i8 - n13;
        float4 v0 = ((const float4*)w2)[j * 2 + 0];
        float4 v1 = ((const float4*)w2)[j * 2 + 1];
        uint4 u;
        u.x = pack2h(v0.x, v0.y); u.y = pack2h(v0.z, v0.w);
        u.z = pack2h(v1.x, v1.y); u.w = pack2h(v1.z, v1.w);
        ((uint4*)d_w2h)[j] = u;
    }
}

// ---------------- mma helper -------------------------------------------------
__device__ __forceinline__ void mma_f16(float* d, const uint32_t* a, const uint32_t* b) {
    asm volatile(
        "mma.sync.aligned.m16n8k16.row.col.f32.f16.f16.f32 "
        "{%0,%1,%2,%3}, {%4,%5,%6,%7}, {%8,%9}, {%0,%1,%2,%3};\n"
        : "+f"(d[0]), "+f"(d[1]), "+f"(d[2]), "+f"(d[3])
        : "r"(a[0]), "r"(a[1]), "r"(a[2]), "r"(a[3]), "r"(b[0]), "r"(b[1]));
}

// ---------------- fp16 GEMM, 256x128 tile, 512 threads, cp.async pipeline ---
// C[pair, n0..] = A_row(pair) . B[e][n]^T ; 256x128 block tile, BK=32,
// 16 warps (4m x 4n), warp tile 64x32 (inner code identical to verified R13).
// cp.async feeds SMEM directly (no prefetch registers -> fits 128-reg cap).
// Each A thread owns halves [hc, hc+16): cp.async at +0 and +16 BYTES (8 halves).
// MODE 0: A = d_xh (row = pair>>1), B = d_w13h, C = d_zh fp16 (stride NF2)
// MODE 1: A = d_acth (row = pair),  B = d_w2h,  C = d_y fp32 (stride HDIM)
#define ROWH 40   // SMEM row stride in halves (80 B); conflict-free
#define AS_OFF(s) ((s) * 10240)
#define BS_OFF(s) (20480 + (s) * 5120)
#define SMEM_HALVES 30720   // 61440 bytes

template<int KDIM, int BROWS, int MODE>
__global__ __launch_bounds__(512)
void gemm_f16_kernel() {
    extern __shared__ __half dynsm[];
    __shared__ int sPair[256];

    const __half* A  = (MODE == 0) ? d_xh   : d_acth;
    const __half* Bw = (MODE == 0) ? d_w13h : d_w2h;
    const int ASHIFT = (MODE == 0) ? 1 : 0;

    int e   = blockIdx.z;
    int cnt = d_count[e];
    int m0  = blockIdx.x * 256;
    if (m0 >= cnt) return;
    int n0  = blockIdx.y * 128;

    int tid = threadIdx.x;
    if (tid < 256) {
        int m = m0 + tid;
        sPair[tid] = d_list[e * T_TOK + (m < cnt ? m : cnt - 1)];
    }
    __syncthreads();

    // A load: 256 rows, 16 halves/thread (2 x cp.async-16, contiguous)
    int aRow = tid >> 1;            // 0..255
    int aHc  = (tid & 1) * 16;      // 0/16
    // B load: 128 rows, 8 halves/thread (1 x cp.async-16)
    int bRow = tid >> 2;            // 0..127
    int bHc  = (tid & 3) * 8;       // 0,8,16,24

    const __half* aPtr = A  + (size_t)(sPair[aRow] >> ASHIFT) * KDIM + aHc;
    const __half* bPtr = Bw + ((size_t)e * BROWS + n0 + bRow) * KDIM + bHc;

    uint32_t smBase = (uint32_t)__cvta_generic_to_shared(dynsm);
    uint32_t aDst = smBase + (aRow * ROWH + aHc) * 2u;
    uint32_t bDst = smBase + (BS_OFF(0) + bRow * ROWH + bHc) * 2u;
    const uint32_t stageA = 10240u * 2u;   // bytes between A stages
    const uint32_t stageB = 5120u * 2u;    // bytes between B stages

    int warp = tid >> 5;            // 0..15
    int lane = tid & 31;
    int wm = warp & 3;              // 4 x 64-row slabs
    int wn = warp >> 2;             // 4 x 32-col slabs
    int g  = lane >> 2;
    int tg = lane & 3;

    float acc[4][4][4];
#pragma unroll
    for (int i = 0; i < 4; i++)
#pragma unroll
        for (int j = 0; j < 4; j++)
#pragma unroll
            for (int r = 0; r < 4; r++) acc[i][j][r] = 0.f;

    // prologue: chunk 0 -> stage 0 via cp.async (16 contiguous halves = 2x16B)
    cp16(aDst,       aPtr);
    cp16(aDst + 16u, aPtr + 8);
    cp16(bDst,       bPtr);
    asm volatile("cp.async.commit_group;");
    asm volatile("cp.async.wait_group 0;");
    __syncthreads();

    const int NCHUNK = KDIM / 32;
    for (int kc = 0; kc < NCHUNK; kc++) {
        int cur = kc & 1;
        bool more = (kc + 1 < NCHUNK);

        // issue loads for chunk kc+1 into the other stage (DMA overlaps MMA)
        if (more) {
            int nxt = cur ^ 1;
            const __half* ap = aPtr + (kc + 1) * 32;
            const __half* bp = bPtr + (kc + 1) * 32;
            cp16(aDst + nxt * stageA,       ap);
            cp16(aDst + nxt * stageA + 16u, ap + 8);
            cp16(bDst + nxt * stageB,       bp);
        }
        asm volatile("cp.async.commit_group;");

        const __half* Acur = &dynsm[AS_OFF(cur)];
        const __half* Bcur = &dynsm[BS_OFF(cur)];
#pragma unroll
        for (int s = 0; s < 2; s++) {
            int k0 = s * 16;
            uint32_t afr[4][4], bfr[4][2];
#pragma unroll
            for (int i = 0; i < 4; i++) {
                int R = wm * 64 + i * 16;
                afr[i][0] = *(const uint32_t*)&Acur[(R + g    ) * ROWH + k0 + 2 * tg    ];
                afr[i][1] = *(const uint32_t*)&Acur[(R + g + 8) * ROWH + k0 + 2 * tg    ];
                afr[i][2] = *(const uint32_t*)&Acur[(R + g    ) * ROWH + k0 + 2 * tg + 8];
                afr[i][3] = *(const uint32_t*)&Acur[(R + g + 8) * ROWH + k0 + 2 * tg + 8];
            }
#pragma unroll
            for (int j = 0; j < 4; j++) {
                int N = wn * 32 + j * 8;
                bfr[j][0] = *(const uint32_t*)&Bcur[(N + g) * ROWH + k0 + 2 * tg    ];
                bfr[j][1] = *(const uint32_t*)&Bcur[(N + g) * ROWH + k0 + 2 * tg + 8];
            }
#pragma unroll
            for (int i = 0; i < 4; i++)
#pragma unroll
                for (int j = 0; j < 4; j++)
                    mma_f16(acc[i][j], afr[i], bfr[j]);
        }

        asm volatile("cp.async.wait_group 0;");
        __syncthreads();
    }

    // epilogue (identical structure to verified R13)
#pragma unroll
    for (int i = 0; i < 4; i++) {
#pragma unroll
        for (int rr = 0; rr < 2; rr++) {
            int mloc = wm * 64 + i * 16 + rr * 8 + g;
            if (m0 + mloc < cnt) {
                int p = sPair[mloc];
                if (MODE == 0) {
                    __half* dst = d_zh + (size_t)p * NF2 + n0 + wn * 32 + tg * 2;
#pragma unroll
                    for (int j = 0; j < 4; j++)
                        *(uint32_t*)(dst + j * 8) =
                            pack2h(acc[i][j][rr * 2 + 0], acc[i][j][rr * 2 + 1]);
                } else {
                    float* dst = d_y + (size_t)p * HDIM + n0 + wn * 32 + tg * 2;
#pragma unroll
                    for (int j = 0; j < 4; j++) {
                        float2 v;
                        v.x = acc[i][j][rr * 2 + 0];
                        v.y = acc[i][j][rr * 2 + 1];
                        *(float2*)(dst + j * 8) = v;
                    }
                }
            }
        }
    }
}

// ---------------- act: silu(g)*u, half in / half out -------------------------
__global__ void act_kernel() {
    int i8 = blockIdx.x * blockDim.x + threadIdx.x;   // over NPAIR*FFND/8
    int p  = i8 >> 9;                                 // / (FFND/8)
    int f8 = i8 & 511;
    if (p >= NPAIR) return;
    const uint4* gp = (const uint4*)(d_zh + (size_t)p * NF2) + f8;
    const uint4* up = (const uint4*)(d_zh + (size_t)p * NF2 + FFND) + f8;
    uint4 gu = *gp, uu = *up, o;
    const __half2* gh = (const __half2*)&gu;
    const __half2* uh = (const __half2*)&uu;
    uint32_t* oh = (uint32_t*)&o;
#pragma unroll
    for (int q = 0; q < 4; q++) {
        float2 gf = __half22float2(gh[q]);
        float2 uf = __half22float2(uh[q]);
        float r0 = gf.x / (1.0f + __expf(-gf.x)) * uf.x;
        float r1 = gf.y / (1.0f + __expf(-gf.y)) * uf.y;
        oh[q] = pack2h(r0, r1);
    }
    ((uint4*)(d_acth + (size_t)p * FFND))[f8] = o;
}

// ---------------- combine: out[t] = w0*y[2t] + w1*y[2t+1] -------------------
__global__ void combine_kernel(float* __restrict__ out) {
    int i4 = blockIdx.x * blockDim.x + threadIdx.x;
    int t  = i4 >> 8;
    int h4 = i4 & 255;
    if (t >= T_TOK) return;
    float w0 = d_wgt[2 * t], w1 = d_wgt[2 * t + 1];
    const float4* y0 = (const float4*)(d_y + (size_t)(2 * t) * HDIM) + h4;
    const float4* y1 = (const float4*)(d_y + (size_t)(2 * t + 1) * HDIM) + h4;
    float4 a = *y0, b = *y1, r;
    r.x = w0 * a.x + w1 * b.x;
    r.y = w0 * a.y + w1 * b.y;
    r.z = w0 * a.z + w1 * b.z;
    r.w = w0 * a.w + w1 * b.w;
    ((float4*)(out + (size_t)t * HDIM))[h4] = r;
}

// ---------------------------------------------------------------------------
extern "C" void kernel_launch(void* const* d_in, const int* in_sizes, int n_in,
                              void* d_out, int out_size) {
    const float* x   = (const float*)d_in[0];
    const float* gw  = (const float*)d_in[1];
    const float* w13 = (const float*)d_in[2];
    const float* w2  = (const float*)d_in[3];
    float* out = (float*)d_out;
    float* rlogits = out + (size_t)T_TOK * HDIM;

    const int smemBytes = SMEM_HALVES * 2;   // 61440
    static int attrDone = 0;
    if (!attrDone) {
        cudaFuncSetAttribute(gemm_f16_kernel<HDIM, NF2, 0>,
                             cudaFuncAttributeMaxDynamicSharedMemorySize, smemBytes);
        cudaFuncSetAttribute(gemm_f16_kernel<FFND, HDIM, 1>,
                             cudaFuncAttributeMaxDynamicSharedMemorySize, smemBytes);
        attrDone = 1;
    }

    zero_counts_kernel<<<1, 32>>>();
    router_kernel<<<T_TOK / 8, 256>>>(x, gw, rlogits);
    convert_x_kernel<<<(T_TOK * HDIM / 8 + 255) / 256, 256>>>(x);
    convert_w_kernel<<<49152, 256>>>(w13, w2);

    // GEMM1 (fp16): z_h = x_h . w13_h[e]^T, K=1024
    dim3 g1(T_TOK / 256, NF2 / 128, NE);      // (8, 64, 8)
    gemm_f16_kernel<HDIM, NF2, 0><<<g1, 512, smemBytes>>>();

    act_kernel<<<(NPAIR * FFND / 8) / 256, 256>>>();

    // GEMM2 (fp16): y = act_h . w2_h[e]^T, K=4096
    dim3 g2(T_TOK / 256, HDIM / 128, NE);     // (8, 8, 8)
    gemm_f16_kernel<FFND, HDIM, 1><<<g2, 512, smemBytes>>>();

    combine_kernel<<<(T_TOK * HDIM / 4) / 256, 256>>>(out);
}

// round 17
// speedup vs baseline: 1.6114x; 1.0128x over previous
#include <cuda_runtime.h>
#include <cuda_fp16.h>
#include <math.h>
#include <stdint.h>

#define T_TOK 2048
#define HDIM  1024
#define FFND  4096
#define NE    8
#define NF2   8192   // 2*FFND
#define NPAIR (2*T_TOK)

// ---------------- scratch (static device globals; no allocation) ------------
// NOTE: never pass these as kernel args from host (host shadow != device ptr).
__device__ int    d_count[NE];
__device__ int    d_list[NE * T_TOK];
__device__ float  d_wgt[NPAIR];
__device__ __half d_xh[(size_t)T_TOK * HDIM];         // x fp16
__device__ __half d_w13h[(size_t)NE * NF2 * HDIM];    // w13 fp16 (128 MB)
__device__ __half d_w2h[(size_t)NE * HDIM * FFND];    // w2 fp16 (64 MB)
__device__ __half d_acth[(size_t)NPAIR * FFND];       // silu(g)*u fp16

// ---------------------------------------------------------------------------
__global__ void zero_counts_kernel() {
    if (threadIdx.x < NE) d_count[threadIdx.x] = 0;
}

// Zero the MoE output region (rlogits region untouched).
__global__ void zero_out_kernel(float* __restrict__ out) {
    int i4 = blockIdx.x * blockDim.x + threadIdx.x;
    if (i4 < T_TOK * HDIM / 4)
        ((float4*)out)[i4] = make_float4(0.f, 0.f, 0.f, 0.f);
}

__device__ __forceinline__ uint32_t pack2h(float lo, float hi) {
    uint32_t r;
    asm("cvt.rn.f16x2.f32 %0, %1, %2;" : "=r"(r) : "f"(hi), "f"(lo));
    return r;
}

__device__ __forceinline__ void cp16(uint32_t smem_dst, const void* gsrc) {
    asm volatile("cp.async.ca.shared.global [%0], [%1], 16;" :: "r"(smem_dst), "l"(gsrc));
}

// One warp per token: router logits, top-2 softmax weights, expert compaction.
__global__ void router_kernel(const float* __restrict__ x,
                              const float* __restrict__ gw,
                              float* __restrict__ rlogits) {
    int gwarp = (blockIdx.x * blockDim.x + threadIdx.x) >> 5;
    int lane  = threadIdx.x & 31;
    if (gwarp >= T_TOK) return;
    const float* xr = x + (size_t)gwarp * HDIM;

    float acc[NE];
#pragma unroll
    for (int e = 0; e < NE; e++) acc[e] = 0.f;
    for (int h = lane; h < HDIM; h += 32) {
        float xv = xr[h];
#pragma unroll
        for (int e = 0; e < NE; e++) acc[e] += xv * gw[e * HDIM + h];
    }
#pragma unroll
    for (int e = 0; e < NE; e++)
#pragma unroll
        for (int off = 16; off; off >>= 1)
            acc[e] += __shfl_xor_sync(0xffffffffu, acc[e], off);

    if (lane == 0) {
#pragma unroll
        for (int e = 0; e < NE; e++) rlogits[gwarp * NE + e] = acc[e];
        int e0 = 0;
#pragma unroll
        for (int e = 1; e < NE; e++) if (acc[e] > acc[e0]) e0 = e;
        int e1 = (e0 == 0) ? 1 : 0;
#pragma unroll
        for (int e = 0; e < NE; e++)
            if (e != e0 && acc[e] > acc[e1]) e1 = e;
        float p1 = __expf(acc[e1] - acc[e0]);
        float inv = 1.0f / (1.0f + p1);
        d_wgt[gwarp * 2 + 0] = inv;
        d_wgt[gwarp * 2 + 1] = p1 * inv;

        int pos0 = atomicAdd(&d_count[e0], 1);
        d_list[e0 * T_TOK + pos0] = gwarp * 2 + 0;
        int pos1 = atomicAdd(&d_count[e1], 1);
        d_list[e1 * T_TOK + pos1] = gwarp * 2 + 1;
    }
}

// Convert x to fp16.
__global__ void convert_x_kernel(const float* __restrict__ x) {
    int i8 = blockIdx.x * blockDim.x + threadIdx.x;   // over T*H/8
    if (i8 >= T_TOK * HDIM / 8) return;
    float4 v0 = ((const float4*)x)[i8 * 2 + 0];
    float4 v1 = ((const float4*)x)[i8 * 2 + 1];
    uint4 u;
    u.x = pack2h(v0.x, v0.y);
    u.y = pack2h(v0.z, v0.w);
    u.z = pack2h(v1.x, v1.y);
    u.w = pack2h(v1.z, v1.w);
    ((uint4*)d_xh)[i8] = u;
}

// Convert w13 + w2 to fp16 (8 floats / thread, single grid).
__global__ void convert_w_kernel(const float* __restrict__ w13,
                                 const float* __restrict__ w2) {
    size_t i8 = (size_t)blockIdx.x * blockDim.x + threadIdx.x;
    const size_t n13 = (size_t)NE * NF2 * HDIM / 8;   // 8388608
    const size_t n2  = (size_t)NE * HDIM * FFND / 8;  // 4194304
    if (i8 < n13) {
        float4 v0 = ((const float4*)w13)[i8 * 2 + 0];
        float4 v1 = ((const float4*)w13)[i8 * 2 + 1];
        uint4 u;
        u.x = pack2h(v0.x, v0.y); u.y = pack2h(v0.z, v0.w);
        u.z = pack2h(v1.x, v1.y); u.w = pack2h(v1.z, v1.w);
        ((uint4*)d_w13h)[i8] = u;
    } else if (i8 < n13 + n2) {
        size_t j = i8 - n13;
        float4 v0 = ((const float4*)w2)[j * 2 + 0];
        float4 v1 = ((const float4*)w2)[j * 2 + 1];
        uint4 u;
        u.x = pack2h(v0.x, v0.y); u.y = pack2h(v0.z, v0.w);
        u.z = pack2h(v1.x, v1.y); u.w = pack2h(v1.z, v1.w);
        ((uint4*)d_w2h)[j] = u;
    }
}

// ---------------- mma helper -------------------------------------------------
__device__ __forceinline__ void mma_f16(float* d, const uint32_t* a, const uint32_t* b) {
    asm volatile(
        "mma.sync.aligned.m16n8k16.row.col.f32.f16.f16.f32 "
        "{%0,%1,%2,%3}, {%4,%5,%6,%7}, {%8,%9}, {%0,%1,%2,%3};\n"
        : "+f"(d[0]), "+f"(d[1]), "+f"(d[2]), "+f"(d[3])
        : "r"(a[0]), "r"(a[1]), "r"(a[2]), "r"(a[3]), "r"(b[0]), "r"(b[1]));
}

// ---------------- fp16 GEMM, 256x128 tile, 512 threads, cp.async pipeline ---
// Inner loop identical to verified R16. MODE differences:
// MODE 0 (GEMM1+act): A = d_xh (row = pair>>1). B tile INTERLEAVED from w13:
//   tile row r -> w13 row (r even ? by*64 + r/2 : FFND + by*64 + r/2).
//   Each thread's acc col pair (even, odd) = (g, u) for the same f ->
//   epilogue computes silu(g)*u in-register, writes d_acth[p][by*64 + q].
// MODE 1 (GEMM2+combine): A = d_acth (row = pair), B = d_w2h rows n0+r.
//   Epilogue: atomicAdd(out[tok][col], wgt[p] * acc) (2 commutative adds/elem
//   -> deterministic; out zeroed by zero_out_kernel).
#define ROWH 40   // SMEM row stride in halves (80 B); conflict-free
#define AS_OFF(s) ((s) * 10240)
#define BS_OFF(s) (20480 + (s) * 5120)
#define SMEM_HALVES 30720   // 61440 bytes

template<int KDIM, int MODE>
__global__ __launch_bounds__(512)
void gemm_f16_kernel(float* __restrict__ outp) {
    extern __shared__ __half dynsm[];
    __shared__ int sPair[256];

    const __half* A  = (MODE == 0) ? d_xh   : d_acth;
    const __half* Bw = (MODE == 0) ? d_w13h : d_w2h;
    const int ASHIFT = (MODE == 0) ? 1 : 0;

    int e   = blockIdx.z;
    int cnt = d_count[e];
    int m0  = blockIdx.x * 256;
    if (m0 >= cnt) return;
    int by  = blockIdx.y;

    int tid = threadIdx.x;
    if (tid < 256) {
        int m = m0 + tid;
        sPair[tid] = d_list[e * T_TOK + (m < cnt ? m : cnt - 1)];
    }
    __syncthreads();

    // A load: 256 rows, 16 halves/thread (2 x cp.async-16, contiguous)
    int aRow = tid >> 1;            // 0..255
    int aHc  = (tid & 1) * 16;      // 0/16
    // B load: 128 tile rows, 8 halves/thread (1 x cp.async-16)
    int bRow = tid >> 2;            // 0..127
    int bHc  = (tid & 3) * 8;       // 0,8,16,24

    // B global row mapping
    size_t bGRow;
    if (MODE == 0) {
        // interleaved gate/up rows: even tile row -> gate f, odd -> up f
        int f = by * 64 + (bRow >> 1);
        bGRow = (size_t)e * NF2 + ((bRow & 1) ? (FFND + f) : f);
    } else {
        bGRow = (size_t)e * HDIM + by * 128 + bRow;
    }

    const __half* aPtr = A  + (size_t)(sPair[aRow] >> ASHIFT) * KDIM + aHc;
    const __half* bPtr = Bw + bGRow * KDIM + bHc;

    uint32_t smBase = (uint32_t)__cvta_generic_to_shared(dynsm);
    uint32_t aDst = smBase + (aRow * ROWH + aHc) * 2u;
    uint32_t bDst = smBase + (BS_OFF(0) + bRow * ROWH + bHc) * 2u;
    const uint32_t stageA = 10240u * 2u;
    const uint32_t stageB = 5120u * 2u;

    int warp = tid >> 5;            // 0..15
    int lane = tid & 31;
    int wm = warp & 3;              // 4 x 64-row slabs
    int wn = warp >> 2;             // 4 x 32-col slabs
    int g  = lane >> 2;
    int tg = lane & 3;

    float acc[4][4][4];
#pragma unroll
    for (int i = 0; i < 4; i++)
#pragma unroll
        for (int j = 0; j < 4; j++)
#pragma unroll
            for (int r = 0; r < 4; r++) acc[i][j][r] = 0.f;

    // prologue: chunk 0 -> stage 0 via cp.async
    cp16(aDst,       aPtr);
    cp16(aDst + 16u, aPtr + 8);
    cp16(bDst,       bPtr);
    asm volatile("cp.async.commit_group;");
    asm volatile("cp.async.wait_group 0;");
    __syncthreads();

    const int NCHUNK = KDIM / 32;
    for (int kc = 0; kc < NCHUNK; kc++) {
        int cur = kc & 1;
        bool more = (kc + 1 < NCHUNK);

        if (more) {
            int nxt = cur ^ 1;
            const __half* ap = aPtr + (kc + 1) * 32;
            const __half* bp = bPtr + (kc + 1) * 32;
            cp16(aDst + nxt * stageA,       ap);
            cp16(aDst + nxt * stageA + 16u, ap + 8);
            cp16(bDst + nxt * stageB,       bp);
        }
        asm volatile("cp.async.commit_group;");

        const __half* Acur = &dynsm[AS_OFF(cur)];
        const __half* Bcur = &dynsm[BS_OFF(cur)];
#pragma unroll
        for (int s = 0; s < 2; s++) {
            int k0 = s * 16;
            uint32_t afr[4][4], bfr[4][2];
#pragma unroll
            for (int i = 0; i < 4; i++) {
                int R = wm * 64 + i * 16;
                afr[i][0] = *(const uint32_t*)&Acur[(R + g    ) * ROWH + k0 + 2 * tg    ];
                afr[i][1] = *(const uint32_t*)&Acur[(R + g + 8) * ROWH + k0 + 2 * tg    ];
                afr[i][2] = *(const uint32_t*)&Acur[(R + g    ) * ROWH + k0 + 2 * tg + 8];
                afr[i][3] = *(const uint32_t*)&Acur[(R + g + 8) * ROWH + k0 + 2 * tg + 8];
            }
#pragma unroll
            for (int j = 0; j < 4; j++) {
                int N = wn * 32 + j * 8;
                bfr[j][0] = *(const uint32_t*)&Bcur[(N + g) * ROWH + k0 + 2 * tg    ];
                bfr[j][1] = *(const uint32_t*)&Bcur[(N + g) * ROWH + k0 + 2 * tg + 8];
            }
#pragma unroll
            for (int i = 0; i < 4; i++)
#pragma unroll
                for (int j = 0; j < 4; j++)
                    mma_f16(acc[i][j], afr[i], bfr[j]);
        }

        asm volatile("cp.async.wait_group 0;");
        __syncthreads();
    }

    // epilogue
#pragma unroll
    for (int i = 0; i < 4; i++) {
#pragma unroll
        for (int rr = 0; rr < 2; rr++) {
            int mloc = wm * 64 + i * 16 + rr * 8 + g;
            if (m0 + mloc < cnt) {
                int p = sPair[mloc];
                if (MODE == 0) {
                    // acc pair (even, odd) = (g, u) for f = by*64 + q,
                    // q = wn*16 + j*4 + tg
                    __half* dst = d_acth + (size_t)p * FFND + by * 64 + wn * 16 + tg;
#pragma unroll
                    for (int j = 0; j < 4; j++) {
                        float gv = acc[i][j][rr * 2 + 0];
                        float uv = acc[i][j][rr * 2 + 1];
                        float val = gv / (1.0f + __expf(-gv)) * uv;
                        dst[j * 4] = __float2half(val);
                    }
                } else {
                    int   t = p >> 1;
                    float w = d_wgt[p];
                    float* dst = outp + (size_t)t * HDIM + by * 128 + wn * 32 + tg * 2;
#pragma unroll
                    for (int j = 0; j < 4; j++) {
                        atomicAdd(dst + j * 8,     w * acc[i][j][rr * 2 + 0]);
                        atomicAdd(dst + j * 8 + 1, w * acc[i][j][rr * 2 + 1]);
                    }
                }
            }
        }
    }
}

// ---------------------------------------------------------------------------
extern "C" void kernel_launch(void* const* d_in, const int* in_sizes, int n_in,
                              void* d_out, int out_size) {
    const float* x   = (const float*)d_in[0];
    const float* gw  = (const float*)d_in[1];
    const float* w13 = (const float*)d_in[2];
    const float* w2  = (const float*)d_in[3];
    float* out = (float*)d_out;
    float* rlogits = out + (size_t)T_TOK * HDIM;

    const int smemBytes = SMEM_HALVES * 2;   // 61440
    static int attrDone = 0;
    if (!attrDone) {
        cudaFuncSetAttribute(gemm_f16_kernel<HDIM, 0>,
                             cudaFuncAttributeMaxDynamicSharedMemorySize, smemBytes);
        cudaFuncSetAttribute(gemm_f16_kernel<FFND, 1>,
                             cudaFuncAttributeMaxDynamicSharedMemorySize, smemBytes);
        attrDone = 1;
    }

    zero_counts_kernel<<<1, 32>>>();
    zero_out_kernel<<<(T_TOK * HDIM / 4 + 255) / 256, 256>>>(out);
    router_kernel<<<T_TOK / 8, 256>>>(x, gw, rlogits);
    convert_x_kernel<<<(T_TOK * HDIM / 8 + 255) / 256, 256>>>(x);
    convert_w_kernel<<<49152, 256>>>(w13, w2);

    // GEMM1 + fused silu*u: d_acth = act(x_h . w13_h[e]^T), K=1024
    // grid.y = 64 tiles of 64 f-columns (128 interleaved g|u output cols each)
    dim3 g1(T_TOK / 256, FFND / 64, NE);      // (8, 64, 8)
    gemm_f16_kernel<HDIM, 0><<<g1, 512, smemBytes>>>(nullptr);

    // GEMM2 + fused combine: out += wgt * (act_h . w2_h[e]^T), K=4096
    dim3 g2(T_TOK / 256, HDIM / 128, NE);     // (8, 8, 8)
    gemm_f16_kernel<FFND, 1><<<g2, 512, smemBytes>>>(out);
}